// round 10
// baseline (speedup 1.0000x reference)
#include <cuda_runtime.h>
#include <cstdint>

__device__ double   g_acc[2];   // [0]=flow0 (kz=3), [1]=flow1 (kz=5)
__device__ unsigned g_cnt = 0;

// Warp-strip separable affine residual, analytic S2, branch-free hot loop:
//   sum_windows p^T (I-P) p
//     = sum_pixels cr(i)*cc(j)*g^2 - sum_windows [ (Sa^2+Sc^2)/D1 + S0^2/D0 ]
// Each lane loads NC contiguous columns at col0 = min(lane*CPT, W-NC) — always
// in-bounds. Duplicate windows/pixels from the shifted last lane are masked by
// loop-invariant predicates and zeroed cc weights. Vertical kz-window sums
// V0/Va per loaded column, incrementally updated (dropped row reloaded from
// L1); slide loads issued before the horizontal sweep. Sa^2 and Sc^2 go to
// SEPARATE accumulators to halve the serial accumulation chain.
template <int KZ, int W, int CPT, int NLD>
__device__ __forceinline__ void strip_residual(const float* __restrict__ plane,
                                               int i0, int rows, int own_hi,
                                               int lane,
                                               float& pA, float& pB, float& wg2) {
    constexpr int   HOUT = W - KZ + 1;
    constexpr int   NC   = NLD * 4;          // columns loaded per lane
    constexpr int   JMAX = NC - KZ + 1;      // computable windows per lane
    constexpr float m    = (KZ - 1) * 0.5f;

    const int col0   = min(lane * CPT, W - NC);   // shifted base: always in-bounds
    const int own_lo = lane * CPT;                // first owned column
    const int own_hc = min(own_lo + CPT, HOUT);   // end of owned output cols

    float ccq[NC];
#pragma unroll
    for (int q = 0; q < NC; ++q) {
        const int jg = col0 + q;
        const bool own = (jg >= own_lo) && (jg < own_lo + CPT);
        const int v = min(jg, KZ - 1) - max(0, jg - (HOUT - 1)) + 1;
        ccq[q] = own ? (float)max(v, 0) : 0.f;
    }

    const float* __restrict__ p = plane + (size_t)i0 * W + col0;

    float V0[NC], Va[NC];
#pragma unroll
    for (int c = 0; c < NC; ++c) { V0[c] = 0.f; Va[c] = 0.f; }

    // ---- init: rows i0 .. i0+KZ-1 (unguarded vector loads) ----
#pragma unroll
    for (int a = 0; a < KZ; ++a) {
        float g[NC];
#pragma unroll
        for (int v = 0; v < NLD; ++v) {
            float4 t = *reinterpret_cast<const float4*>(p + (size_t)a * W + v * 4);
            g[v*4+0] = t.x; g[v*4+1] = t.y; g[v*4+2] = t.z; g[v*4+3] = t.w;
        }
        const int rg = i0 + a;
        const float crf = (rg < own_hi)
            ? (float)max(min(rg, KZ - 1) - max(0, rg - (HOUT - 1)) + 1, 0) : 0.f;
        float rowacc = 0.f;
#pragma unroll
        for (int q = 0; q < NC; ++q) {
            V0[q] += g[q];
            Va[q] = fmaf((float)a - m, g[q], Va[q]);
            rowacc = fmaf(ccq[q], g[q] * g[q], rowacc);
        }
        wg2 = fmaf(crf, rowacc, wg2);
    }

    float pAa = 0.f, pAc = 0.f;      // split accumulator chains

    // ---- main loop over output rows ----
    for (int ii = 0; ii < rows; ++ii) {
        const bool doSlide = (ii + 1 < rows);

        // Issue next-slide loads FIRST (consumed after the sweep below).
        float gn[NC], gd[NC];
        if (doSlide) {
            const float* pn = p + (size_t)(ii + KZ) * W;
            const float* po = p + (size_t)ii * W;
#pragma unroll
            for (int v = 0; v < NLD; ++v) {
                float4 tn = *reinterpret_cast<const float4*>(pn + v * 4);
                float4 to = *reinterpret_cast<const float4*>(po + v * 4);
                gn[v*4+0]=tn.x; gn[v*4+1]=tn.y; gn[v*4+2]=tn.z; gn[v*4+3]=tn.w;
                gd[v*4+0]=to.x; gd[v*4+1]=to.y; gd[v*4+2]=to.z; gd[v*4+3]=to.w;
            }
        }

        // Horizontal sliding windows (independent of the loads above).
        float S0 = 0.f, Sa = 0.f, Sc = 0.f;
#pragma unroll
        for (int c = 0; c < KZ; ++c) {
            S0 += V0[c];
            Sc = fmaf((float)c - m, V0[c], Sc);
            Sa += Va[c];
        }
#pragma unroll
        for (int j = 0; j < JMAX; ++j) {
            const int jg = col0 + j;                    // loop-invariant preds
            if (jg >= own_lo && jg < own_hc) {
                pAa = fmaf(Sa, Sa, pAa);
                pAc = fmaf(Sc, Sc, pAc);
                pB  = fmaf(S0, S0, pB);
            }
            if (j + 1 < JMAX) {
                const float d0 = V0[j], dn = V0[j + KZ];
                Sc = Sc - S0;
                Sc = fmaf(m + 1.f, d0, Sc);
                Sc = fmaf(m, dn, Sc);
                S0 += dn - d0;
                Sa += Va[j + KZ] - Va[j];
            }
        }

        // Vertical slide using the preloaded rows.
        if (doSlide) {
            const int rg = i0 + ii + KZ;
            const float crf = (rg < own_hi)
                ? (float)max(min(rg, KZ - 1) - max(0, rg - (HOUT - 1)) + 1, 0) : 0.f;
            float rowacc = 0.f;
#pragma unroll
            for (int q = 0; q < NC; ++q) {
                float t = Va[q] - V0[q];
                t = fmaf(m + 1.f, gd[q], t);
                Va[q] = fmaf(m, gn[q], t);
                V0[q] += gn[q] - gd[q];
                rowacc = fmaf(ccq[q], gn[q] * gn[q], rowacc);
            }
            wg2 = fmaf(crf, rowacc, wg2);
        }
    }
    pA += pAa + pAc;
}

// 296 blocks x 8 warps = 2368 warps; exactly 2 blocks per SM.
// TIME-PHASED: every warp runs one heavy task (kz=5, flow1), then one light
// task (kz=3, flow0). At any instant an SMSP executes only one code body.
//   heavy: 2368 tasks = 64 planes x 37 chunks (30 of 7 rows + 7 of 6 = 252).
//   light: 2368 tasks = 64 planes x 37 chunks (15 of 4 rows + 22 of 3 = 126).
__global__ __launch_bounds__(256, 2)
void fused_loss_kernel(const float* __restrict__ f0,
                       const float* __restrict__ f1,
                       float* __restrict__ out) {
    const int wid  = threadIdx.x >> 5;
    const int lane = threadIdx.x & 31;
    const int t    = blockIdx.x * 8 + wid;        // 0..2367
    const int plane = t / 37;
    const int c     = t % 37;

    // ---- phase 1: heavy (kz=5 on flow1) ----
    float pA = 0.f, pB = 0.f, wg2 = 0.f;
    {
        int i0, rows;
        if (c < 30) { i0 = c * 7;              rows = 7; }
        else        { i0 = 210 + (c - 30) * 6; rows = 6; }
        const int own_hi = (c == 36) ? 256 : (i0 + rows);
        strip_residual<5, 256, 8, 3>(f1 + (size_t)plane * 256 * 256,
                                     i0, rows, own_hi, lane, pA, pB, wg2);
    }
    constexpr float invD1h = 12.0f / (25.0f * 24.0f);
    constexpr float invD0h = 1.0f / 25.0f;
    float partial1 = wg2 - pA * invD1h - pB * invD0h;

    // ---- phase 2: light (kz=3 on flow0) ----
    pA = 0.f; pB = 0.f; wg2 = 0.f;
    {
        int i0, rows;
        if (c < 15) { i0 = c * 4;             rows = 4; }
        else        { i0 = 60 + (c - 15) * 3; rows = 3; }
        const int own_hi = (c == 36) ? 128 : (i0 + rows);
        strip_residual<3, 128, 4, 2>(f0 + (size_t)plane * 128 * 128,
                                     i0, rows, own_hi, lane, pA, pB, wg2);
    }
    constexpr float invD1l = 12.0f / (9.0f * 8.0f);
    constexpr float invD0l = 1.0f / 9.0f;
    float partial0 = wg2 - pA * invD1l - pB * invD0l;

    // ---- reduction ----
#pragma unroll
    for (int off = 16; off > 0; off >>= 1) {
        partial1 += __shfl_down_sync(0xffffffffu, partial1, off);
        partial0 += __shfl_down_sync(0xffffffffu, partial0, off);
    }

    __shared__ double sh1[8], sh0[8];
    if (lane == 0) { sh1[wid] = (double)partial1; sh0[wid] = (double)partial0; }
    __syncthreads();

    if (threadIdx.x == 0) {
        double a1 = 0.0, a0 = 0.0;
#pragma unroll
        for (int w = 0; w < 8; ++w) { a1 += sh1[w]; a0 += sh0[w]; }
        atomicAdd(&g_acc[0], a0);
        atomicAdd(&g_acc[1], a1);
        __threadfence();
        const unsigned done = atomicAdd(&g_cnt, 1);
        if (done == gridDim.x - 1) {              // last block: finalize + reset
            __threadfence();
            const double r0 = g_acc[0], r1 = g_acc[1];
            out[0] = (float)(r0 / (32.0 * 126.0 * 126.0) +
                             r1 / (32.0 * 252.0 * 252.0));
            g_acc[0] = 0.0; g_acc[1] = 0.0; g_cnt = 0u;
        }
    }
}

extern "C" void kernel_launch(void* const* d_in, const int* in_sizes, int n_in,
                              void* d_out, int out_size) {
    const float* flow0 = (const float*)d_in[0];  // (32, 2, 128, 128)
    const float* flow1 = (const float*)d_in[1];  // (32, 2, 256, 256)
    if (n_in >= 2 && in_sizes[0] > in_sizes[1]) {
        const float* t = flow0; flow0 = flow1; flow1 = t;
    }
    fused_loss_kernel<<<296, 256>>>(flow0, flow1, (float*)d_out);
}

// round 15
// speedup vs baseline: 1.9720x; 1.9720x over previous
#include <cuda_runtime.h>
#include <cstdint>

__device__ double   g_acc[2];   // [0]=flow0 (kz=3), [1]=flow1 (kz=5)
__device__ unsigned g_cnt = 0;

// Warp-strip separable affine residual, analytic S2, branch-free hot loop:
//   sum_windows p^T (I-P) p
//     = sum_pixels cr(i)*cc(j)*g^2 - sum_windows [ (Sa^2+Sc^2)/D1 + S0^2/D0 ]
// Each lane loads NC contiguous columns at col0 = min(lane*CPT, W-NC) — always
// in-bounds. Duplicate windows/pixels from the shifted last lane are masked by
// loop-invariant predicates and zeroed cc weights. Vertical kz-window sums
// V0/Va per loaded column, incrementally updated (dropped row reloaded from
// L1); slide loads issued before the horizontal sweep. ROWS is compile-time:
// the row loop fully unrolls, all slide/guard branches vanish.
template <int KZ, int W, int CPT, int NLD, int ROWS>
__device__ __forceinline__ void strip_residual(const float* __restrict__ plane,
                                               int i0, int own_hi, int lane,
                                               float& pA, float& pB, float& wg2) {
    constexpr int   HOUT = W - KZ + 1;
    constexpr int   NC   = NLD * 4;          // columns loaded per lane
    constexpr int   JMAX = NC - KZ + 1;      // computable windows per lane
    constexpr float m    = (KZ - 1) * 0.5f;

    const int col0   = min(lane * CPT, W - NC);   // shifted base: always in-bounds
    const int own_lo = lane * CPT;                // first owned column
    const int own_hc = min(own_lo + CPT, HOUT);   // end of owned output cols

    float ccq[NC];
#pragma unroll
    for (int q = 0; q < NC; ++q) {
        const int jg = col0 + q;
        const bool own = (jg >= own_lo) && (jg < own_lo + CPT);
        const int v = min(jg, KZ - 1) - max(0, jg - (HOUT - 1)) + 1;
        ccq[q] = own ? (float)max(v, 0) : 0.f;
    }

    const float* __restrict__ p = plane + (size_t)i0 * W + col0;

    float V0[NC], Va[NC];
#pragma unroll
    for (int c = 0; c < NC; ++c) { V0[c] = 0.f; Va[c] = 0.f; }

    // ---- init: rows i0 .. i0+KZ-1 (unguarded vector loads) ----
#pragma unroll
    for (int a = 0; a < KZ; ++a) {
        float g[NC];
#pragma unroll
        for (int v = 0; v < NLD; ++v) {
            float4 t = *reinterpret_cast<const float4*>(p + (size_t)a * W + v * 4);
            g[v*4+0] = t.x; g[v*4+1] = t.y; g[v*4+2] = t.z; g[v*4+3] = t.w;
        }
        const int rg = i0 + a;
        const float crf = (rg < own_hi)
            ? (float)max(min(rg, KZ - 1) - max(0, rg - (HOUT - 1)) + 1, 0) : 0.f;
        float rowacc = 0.f;
#pragma unroll
        for (int q = 0; q < NC; ++q) {
            V0[q] += g[q];
            Va[q] = fmaf((float)a - m, g[q], Va[q]);
            rowacc = fmaf(ccq[q], g[q] * g[q], rowacc);
        }
        wg2 = fmaf(crf, rowacc, wg2);
    }

    float pAa = 0.f, pAc = 0.f;      // split accumulator chains

    // ---- main loop over output rows (fully unrolled, branch-free) ----
#pragma unroll
    for (int ii = 0; ii < ROWS; ++ii) {
        constexpr bool always = true;
        const bool doSlide = (ii + 1 < ROWS) && always;   // compile-time

        // Issue next-slide loads FIRST (consumed after the sweep below).
        float gn[NC], gd[NC];
        if (doSlide) {
            const float* pn = p + (size_t)(ii + KZ) * W;
            const float* po = p + (size_t)ii * W;
#pragma unroll
            for (int v = 0; v < NLD; ++v) {
                float4 tn = *reinterpret_cast<const float4*>(pn + v * 4);
                float4 to = *reinterpret_cast<const float4*>(po + v * 4);
                gn[v*4+0]=tn.x; gn[v*4+1]=tn.y; gn[v*4+2]=tn.z; gn[v*4+3]=tn.w;
                gd[v*4+0]=to.x; gd[v*4+1]=to.y; gd[v*4+2]=to.z; gd[v*4+3]=to.w;
            }
        }

        // Horizontal sliding windows (independent of the loads above).
        float S0 = 0.f, Sa = 0.f, Sc = 0.f;
#pragma unroll
        for (int c = 0; c < KZ; ++c) {
            S0 += V0[c];
            Sc = fmaf((float)c - m, V0[c], Sc);
            Sa += Va[c];
        }
#pragma unroll
        for (int j = 0; j < JMAX; ++j) {
            const int jg = col0 + j;                    // loop-invariant preds
            if (jg >= own_lo && jg < own_hc) {
                pAa = fmaf(Sa, Sa, pAa);
                pAc = fmaf(Sc, Sc, pAc);
                pB  = fmaf(S0, S0, pB);
            }
            if (j + 1 < JMAX) {
                const float d0 = V0[j], dn = V0[j + KZ];
                Sc = Sc - S0;
                Sc = fmaf(m + 1.f, d0, Sc);
                Sc = fmaf(m, dn, Sc);
                S0 += dn - d0;
                Sa += Va[j + KZ] - Va[j];
            }
        }

        // Vertical slide using the preloaded rows.
        if (doSlide) {
            const int rg = i0 + ii + KZ;
            const float crf = (rg < own_hi)
                ? (float)max(min(rg, KZ - 1) - max(0, rg - (HOUT - 1)) + 1, 0) : 0.f;
            float rowacc = 0.f;
#pragma unroll
            for (int q = 0; q < NC; ++q) {
                float t = Va[q] - V0[q];
                t = fmaf(m + 1.f, gd[q], t);
                Va[q] = fmaf(m, gn[q], t);
                V0[q] += gn[q] - gd[q];
                rowacc = fmaf(ccq[q], gn[q] * gn[q], rowacc);
            }
            wg2 = fmaf(crf, rowacc, wg2);
        }
    }
    pA += pAa + pAc;
}

// 296 blocks x 8 warps = 2368 warps = 64 planes x 37 tasks; exactly 2
// blocks/SM. Per plane: 28 heavy chunks of EXACTLY 9 rows (28*9=252, kz=5,
// flow1) + 9 light chunks of EXACTLY 14 rows (9*14=126, kz=3, flow0).
// Uniform compile-time chunk sizes -> fully unrolled branch-free bodies.
__global__ __launch_bounds__(256, 2)
void fused_loss_kernel(const float* __restrict__ f0,
                       const float* __restrict__ f1,
                       float* __restrict__ out) {
    const int wid  = threadIdx.x >> 5;
    const int lane = threadIdx.x & 31;
    const int t    = blockIdx.x * 8 + wid;        // 0..2367
    const int plane = t / 37;
    const int c     = t % 37;

    float pA = 0.f, pB = 0.f, wg2 = 0.f;
    float partial;
    bool heavy = (c < 28);

    if (heavy) {                                  // kz=5 on flow1, 9-row chunk
        const int i0     = c * 9;
        const int own_hi = (c == 27) ? 256 : (i0 + 9);
        strip_residual<5, 256, 8, 3, 9>(f1 + (size_t)plane * 256 * 256,
                                        i0, own_hi, lane, pA, pB, wg2);
        constexpr float invD1 = 12.0f / (25.0f * 24.0f);
        constexpr float invD0 = 1.0f / 25.0f;
        partial = wg2 - pA * invD1 - pB * invD0;
    } else {                                      // kz=3 on flow0, 14-row chunk
        const int lc     = c - 28;
        const int i0     = lc * 14;
        const int own_hi = (lc == 8) ? 128 : (i0 + 14);
        strip_residual<3, 128, 4, 2, 14>(f0 + (size_t)plane * 128 * 128,
                                         i0, own_hi, lane, pA, pB, wg2);
        constexpr float invD1 = 12.0f / (9.0f * 8.0f);
        constexpr float invD0 = 1.0f / 9.0f;
        partial = wg2 - pA * invD1 - pB * invD0;
    }

#pragma unroll
    for (int off = 16; off > 0; off >>= 1)
        partial += __shfl_down_sync(0xffffffffu, partial, off);

    __shared__ double sh[8];
    __shared__ int    shw[8];
    if (lane == 0) { sh[wid] = (double)partial; shw[wid] = heavy ? 1 : 0; }
    __syncthreads();

    if (threadIdx.x == 0) {
        double a1 = 0.0, a0 = 0.0;
#pragma unroll
        for (int w = 0; w < 8; ++w) {
            if (shw[w]) a1 += sh[w]; else a0 += sh[w];
        }
        atomicAdd(&g_acc[0], a0);
        atomicAdd(&g_acc[1], a1);
        __threadfence();
        const unsigned done = atomicAdd(&g_cnt, 1);
        if (done == gridDim.x - 1) {              // last block: finalize + reset
            __threadfence();
            const double r0 = g_acc[0], r1 = g_acc[1];
            out[0] = (float)(r0 / (32.0 * 126.0 * 126.0) +
                             r1 / (32.0 * 252.0 * 252.0));
            g_acc[0] = 0.0; g_acc[1] = 0.0; g_cnt = 0u;
        }
    }
}

extern "C" void kernel_launch(void* const* d_in, const int* in_sizes, int n_in,
                              void* d_out, int out_size) {
    const float* flow0 = (const float*)d_in[0];  // (32, 2, 128, 128)
    const float* flow1 = (const float*)d_in[1];  // (32, 2, 256, 256)
    if (n_in >= 2 && in_sizes[0] > in_sizes[1]) {
        const float* t = flow0; flow0 = flow1; flow1 = t;
    }
    fused_loss_kernel<<<296, 256>>>(flow0, flow1, (float*)d_out);
}